// round 9
// baseline (speedup 1.0000x reference)
#include <cuda_runtime.h>
#include <math.h>

#define NPLANES 24
#define H0 1280
#define W0 1280

// ---------------------------------------------------------------------------
// Scratch
// ---------------------------------------------------------------------------
__device__ float g_pyr1[NPLANES * 640 * 640];
__device__ float g_pyr2[NPLANES * 320 * 320];
__device__ float g_t80[3 * NPLANES * 80 * 80];   // filter results at 80 level

__device__ __forceinline__ int refl101(int i, int n) {
    if (i < 0) i = -i;
    if (i >= n) i = 2 * n - 2 - i;
    return i;
}

// ---------------------------------------------------------------------------
// f32x2 packed helpers (Blackwell)
// ---------------------------------------------------------------------------
typedef unsigned long long ull;
__device__ __forceinline__ ull pk2(float a, float b) {
    ull r;
    asm("mov.b64 %0, {%1, %2};" : "=l"(r)
        : "r"(__float_as_uint(a)), "r"(__float_as_uint(b)));
    return r;
}
__device__ __forceinline__ void upk2(ull v, float& a, float& b) {
    unsigned int lo, hi;
    asm("mov.b64 {%0, %1}, %2;" : "=r"(lo), "=r"(hi) : "l"(v));
    a = __uint_as_float(lo);
    b = __uint_as_float(hi);
}
__device__ __forceinline__ ull fma2(ull a, ull b, ull c) {
    ull r;
    asm("fma.rn.f32x2 %0, %1, %2, %3;" : "=l"(r) : "l"(a), "l"(b), "l"(c));
    return r;
}
__device__ __forceinline__ ull mul2(ull a, ull b) {
    ull r;
    asm("mul.rn.f32x2 %0, %1, %2;" : "=l"(r) : "l"(a), "l"(b));
    return r;
}

// ---------------------------------------------------------------------------
// pyrDown, 4x4 outputs/thread: 11 input rows x 4 float4 loads -> 16 outputs.
// 5x5 binomial, reflect-101 pad 2, stride 2.
// ---------------------------------------------------------------------------
__global__ void __launch_bounds__(256)
pyrdown16_kernel(const float* __restrict__ src,
                 float* __restrict__ dst, int H, int W) {
    const int Ho = H >> 1, Wo = W >> 1;
    const int Wq = Wo >> 2, Hq = Ho >> 2;
    const int total = NPLANES * Hq * Wq;
    int idx = blockIdx.x * blockDim.x + threadIdx.x;
    if (idx >= total) return;
    int wq = idx % Wq;
    int t  = idx / Wq;
    int hq = t % Hq;
    int p  = t / Hq;
    int ho0 = hq << 2, wo0 = wq << 2;

    const float* s = src + (size_t)p * H * W;
    const float kk[5] = {0.0625f, 0.25f, 0.375f, 0.25f, 0.0625f};
    float* dbase = dst + (size_t)p * Ho * Wo;

    bool interior = (ho0 >= 1) && (2 * ho0 + 8 <= H - 1) &&
                    (wq >= 1) && (8 * wq + 11 <= W - 1);
    if (interior) {
        float hs[11][4];
        const float* rowp = s + (size_t)(2 * ho0 - 2) * W + (8 * wq - 4);
#pragma unroll
        for (int r = 0; r < 11; r++, rowp += W) {
            const float4* r4 = (const float4*)rowp;
            float4 A = r4[0], Bv = r4[1], C = r4[2], D = r4[3];
            float v[16] = {A.x, A.y, A.z, A.w, Bv.x, Bv.y, Bv.z, Bv.w,
                           C.x, C.y, C.z, C.w, D.x, D.y, D.z, D.w};
#pragma unroll
            for (int o = 0; o < 4; o++)
                hs[r][o] = 0.0625f * (v[2 * o + 2] + v[2 * o + 6])
                         + 0.25f   * (v[2 * o + 3] + v[2 * o + 5])
                         + 0.375f  *  v[2 * o + 4];
        }
#pragma unroll
        for (int ry = 0; ry < 4; ry++) {
            float4 o4;
            float* acc = (float*)&o4;
#pragma unroll
            for (int o = 0; o < 4; o++) {
                float a = 0.f;
#pragma unroll
                for (int dy = 0; dy < 5; dy++)
                    a += kk[dy] * hs[2 * ry + dy][o];
                acc[o] = a;
            }
            *(float4*)(dbase + (size_t)(ho0 + ry) * Wo + wo0) = o4;
        }
    } else {
#pragma unroll
        for (int ry = 0; ry < 4; ry++) {
            int ho = ho0 + ry;
            float4 o4;
            float* acc = (float*)&o4;
#pragma unroll
            for (int o = 0; o < 4; o++) {
                int wo = wo0 + o;
                float a = 0.f;
#pragma unroll
                for (int dy = 0; dy < 5; dy++) {
                    int y = refl101(2 * ho + dy - 2, H);
                    const float* row = s + (size_t)y * W;
                    float r2 = 0.f;
#pragma unroll
                    for (int dx = 0; dx < 5; dx++)
                        r2 += kk[dx] * row[refl101(2 * wo + dx - 2, W)];
                    a += kk[dy] * r2;
                }
                acc[o] = a;
            }
            *(float4*)(dbase + (size_t)ho * Wo + wo0) = o4;
        }
    }
}

// ---------------------------------------------------------------------------
// Generic-pointer per-plane helpers (smem or gmem)
// ---------------------------------------------------------------------------
__device__ void pyrdown_plane(const float* s, float* d, int N, int tid, int nt) {
    const int No = N >> 1;
    const int total = No * No;
    const float kk[5] = {0.0625f, 0.25f, 0.375f, 0.25f, 0.0625f};
    for (int idx = tid; idx < total; idx += nt) {
        int wo = idx % No, ho = idx / No;
        float acc = 0.f;
#pragma unroll
        for (int dy = 0; dy < 5; dy++) {
            int y = refl101(2 * ho + dy - 2, N);
            const float* row = s + y * N;
            float r = 0.f;
#pragma unroll
            for (int dx = 0; dx < 5; dx++)
                r += kk[dx] * row[refl101(2 * wo + dx - 2, N)];
            acc += kk[dy] * r;
        }
        d[idx] = acc;
    }
}

__device__ void up2_plane(const float* s, float* d, int N, int tid, int nt) {
    const int No = 2 * N;
    const int total = No * No;
    for (int idx = tid; idx < total; idx += nt) {
        int wo = idx % No, ho = idx / No;
        int iy = (ho >> 1) + (ho & 1) - 1;
        float fy = (ho & 1) ? 0.25f : 0.75f;
        int y0 = max(iy, 0), y1 = min(iy + 1, N - 1);
        int ix = (wo >> 1) + (wo & 1) - 1;
        float fx = (wo & 1) ? 0.25f : 0.75f;
        int x0 = max(ix, 0), x1 = min(ix + 1, N - 1);
        float v00 = s[y0 * N + x0], v01 = s[y0 * N + x1];
        float v10 = s[y1 * N + x0], v11 = s[y1 * N + x1];
        float tp = v00 + fx * (v01 - v00);
        float bt = v10 + fx * (v11 - v10);
        d[idx] = tp + fy * (bt - tp);
    }
}

__device__ void blur_plane(const float* s, float* d, int N, int ks,
                           int tid, int nt) {
    float g[9];
    float sg = 0.3f * ((ks - 1) * 0.5f - 1.f) + 0.8f;
    float inv2s2 = 1.f / (2.f * sg * sg);
    float sum = 0.f;
    for (int i = 0; i < ks; i++) {
        float dd = (float)i - (ks - 1) * 0.5f;
        g[i] = expf(-dd * dd * inv2s2);
        sum += g[i];
    }
    float inv = 1.f / sum;
    for (int i = 0; i < ks; i++) g[i] *= inv;

    int P = ks / 2;
    const int total = N * N;
    for (int idx = tid; idx < total; idx += nt) {
        int w = idx % N, h = idx / N;
        float acc = 0.f;
        for (int dy = 0; dy < ks; dy++) {
            int y = refl101(h + dy - P, N);
            const float* row = s + y * N;
            float r = 0.f;
            for (int dx = 0; dx < ks; dx++)
                r += g[dx] * row[refl101(w + dx - P, N)];
            acc += g[dy] * r;
        }
        d[idx] = acc;
    }
}

// ---------------------------------------------------------------------------
// prep: block = (plane, sigma). Reads the 320-level plane from gmem, builds
// the whole small pyramid + blur + up-chain in dynamic smem (149 KB),
// writes only the 80-level filter result to gmem.
// smem float offsets: s160=0, s80=25600, s40=32000, s20=33600, s10=34000,
//                     s5=34100, A=34125, B=35725. total=37325 floats.
// ---------------------------------------------------------------------------
__global__ void __launch_bounds__(256)
prep_kernel(const float* __restrict__ p2, float* __restrict__ t80) {
    extern __shared__ float sm[];
    float* s160 = sm;
    float* s80  = sm + 25600;
    float* s40  = sm + 32000;
    float* s20  = sm + 33600;
    float* s10  = sm + 34000;
    float* s5   = sm + 34100;
    float* A    = sm + 34125;
    float* B    = sm + 35725;

    int p = blockIdx.x;
    int sg = blockIdx.y;
    int tid = threadIdx.x, nt = blockDim.x;

    pyrdown_plane(p2 + (size_t)p * 102400, s160, 320, tid, nt);
    __syncthreads();
    pyrdown_plane(s160, s80, 160, tid, nt);
    __syncthreads();
    pyrdown_plane(s80, s40, 80, tid, nt);
    __syncthreads();
    if (sg >= 1) {
        pyrdown_plane(s40, s20, 40, tid, nt);
        __syncthreads();
        pyrdown_plane(s20, s10, 20, tid, nt);
        __syncthreads();
    }
    if (sg == 2) {
        pyrdown_plane(s10, s5, 10, tid, nt);
        __syncthreads();
    }

    float* T = t80 + ((size_t)sg * NPLANES + p) * 6400;

    if (sg == 0) {
        blur_plane(s40, A, 40, 7, tid, nt); __syncthreads();
        up2_plane(A, T, 40, tid, nt);
    } else if (sg == 1) {
        blur_plane(s10, A, 10, 9, tid, nt); __syncthreads();
        up2_plane(A, B, 10, tid, nt); __syncthreads();
        up2_plane(B, A, 20, tid, nt); __syncthreads();
        up2_plane(A, T, 40, tid, nt);
    } else {
        blur_plane(s5, A, 5, 9, tid, nt); __syncthreads();
        up2_plane(A, B, 5, tid, nt); __syncthreads();
        up2_plane(B, A, 10, tid, nt); __syncthreads();
        up2_plane(A, B, 20, tid, nt); __syncthreads();
        up2_plane(B, T, 40, tid, nt);
    }
}

// ---------------------------------------------------------------------------
// Polyphase double-up weights: output row 4m+ph draws source rows {m-1,m,m+1}.
// ---------------------------------------------------------------------------
__device__ __constant__ float W4[4][3] = {
    {0.375f,  0.625f, 0.f},
    {0.1875f, 0.75f,  0.0625f},
    {0.0625f, 0.75f,  0.1875f},
    {0.f,     0.625f, 0.375f}
};

// ---------------------------------------------------------------------------
// Composite with fused pack: block = 16x16 320-cells of one image.
//  Stage A: compute 18x18 (halo) pack tile {f30,f150,f300} at 320 level from
//           t80 (polyphase 80->320) into smem.
//  Stage B: per thread (one 320-cell): polyphase 320->1280 from the smem
//           3x3 patch + retinex + color restoration, 4x4 pixels, 3 channels.
// ---------------------------------------------------------------------------
__global__ void __launch_bounds__(256)
composite_kernel(const float* __restrict__ x,
                 const float* __restrict__ t80,
                 float* __restrict__ out) {
    __shared__ float4 SP[3][18 * 19];

    int n   = blockIdx.z;
    int bm0 = blockIdx.y * 16;
    int bq0 = blockIdx.x * 16;
    int tid = threadIdx.x;

    // ---- Stage A: pack tile (18x18 incl. halo) per channel ----
    for (int task = tid; task < 3 * 324; task += 256) {
        int c = task / 324;
        int cell = task - c * 324;
        int hi = cell / 18, hj = cell - hi * 18;
        int M = min(max(bm0 - 1 + hi, 0), 319);
        int Q = min(max(bq0 - 1 + hj, 0), 319);
        int m = M >> 2, phm = M & 3;
        int q = Q >> 2, phq = Q & 3;
        int mr0 = max(m - 1, 0) * 80, mr1 = m * 80, mr2 = min(m + 1, 79) * 80;
        int qc0 = max(q - 1, 0), qc1 = q, qc2 = min(q + 1, 79);
        float wy0 = W4[phm][0], wy1 = W4[phm][1], wy2 = W4[phm][2];
        float wx0 = W4[phq][0], wx1 = W4[phq][1], wx2 = W4[phq][2];
        float v[3];
#pragma unroll
        for (int s = 0; s < 3; s++) {
            const float* f = t80 + ((size_t)s * NPLANES + n * 3 + c) * 6400;
            float R0 = wy0 * f[mr0 + qc0] + wy1 * f[mr1 + qc0] + wy2 * f[mr2 + qc0];
            float R1 = wy0 * f[mr0 + qc1] + wy1 * f[mr1 + qc1] + wy2 * f[mr2 + qc1];
            float R2 = wy0 * f[mr0 + qc2] + wy1 * f[mr1 + qc2] + wy2 * f[mr2 + qc2];
            v[s] = wx0 * R0 + wx1 * R1 + wx2 * R2;
        }
        SP[c][hi * 19 + hj] = make_float4(v[0], v[1], v[2], 0.f);
    }
    __syncthreads();

    // ---- Stage B ----
    int ty = tid >> 4, tx = tid & 15;
    int m = bm0 + ty, q = bq0 + tx;

    const float EPS = 1e-6f;
    const float LOG10_2 = 0.30102999566398f;

    ull w2p[4][3];
#pragma unroll
    for (int ph = 0; ph < 4; ph++)
#pragma unroll
        for (int k = 0; k < 3; k++)
            w2p[ph][k] = pk2(W4[ph][k], W4[ph][k]);

    float lp[3][16];

#pragma unroll
    for (int c = 0; c < 3; c++) {
        ull Pab[3][3];
        float Pz[3][3];
#pragma unroll
        for (int a = 0; a < 3; a++)
#pragma unroll
            for (int b = 0; b < 3; b++) {
                float4 v = SP[c][(ty + a) * 19 + (tx + b)];
                Pab[a][b] = pk2(v.x, v.y);
                Pz[a][b]  = v.z;
            }

#pragma unroll
        for (int py = 0; py < 4; py++) {
            float w0 = W4[py][0], w1 = W4[py][1], w2 = W4[py][2];
            ull Rab[3];
            float Rz[3];
#pragma unroll
            for (int b = 0; b < 3; b++) {
                Rab[b] = fma2(Pab[2][b], w2p[py][2],
                         fma2(Pab[1][b], w2p[py][1],
                         mul2(Pab[0][b], w2p[py][0])));
                Rz[b] = w0 * Pz[0][b] + w1 * Pz[1][b] + w2 * Pz[2][b];
            }
#pragma unroll
            for (int px = 0; px < 4; px++) {
                ull vab = fma2(Rab[2], w2p[px][2],
                          fma2(Rab[1], w2p[px][1],
                          mul2(Rab[0], w2p[px][0])));
                float u0 = W4[px][0], u1 = W4[px][1], u2 = W4[px][2];
                float vz = u0 * Rz[0] + u1 * Rz[1] + u2 * Rz[2];
                float vx, vy;
                upk2(vab, vx, vy);
                float a  = 255.f * vx + 1.f;
                float b  = 255.f * vy + 1.f;
                float cc = 255.f * vz + 1.f;
                lp[c][py * 4 + px] = __log2f((a + EPS) * (b + EPS) * (cc + EPS));
            }
        }
    }

#pragma unroll
    for (int py = 0; py < 4; py++) {
        float4 xr[3];
#pragma unroll
        for (int c = 0; c < 3; c++)
            xr[c] = *(const float4*)(x + (size_t)(n * 3 + c) * H0 * W0
                                       + (size_t)(4 * m + py) * W0 + 4 * q);
        float4 o[3];
#pragma unroll
        for (int px = 0; px < 4; px++) {
            float im0 = ((const float*)&xr[0])[px] * 255.f + 1.f;
            float im1 = ((const float*)&xr[1])[px] * 255.f + 1.f;
            float im2 = ((const float*)&xr[2])[px] * 255.f + 1.f;
            float inv_sum = 2.f / (im0 + im1 + im2 + EPS);
            float im[3] = {im0, im1, im2};
#pragma unroll
            for (int c = 0; c < 3; c++) {
                float retinex = (__log2f(im[c] + EPS)
                               - lp[c][py * 4 + px] * (1.f / 3.f)) * LOG10_2;
                float cr = __log2f(im[c] * inv_sum + 1.f) * LOG10_2;
                float e = retinex * cr * 2700.f + 128.f;
                e = fminf(fmaxf(e, 0.f), 255.f);
                ((float*)&o[c])[px] = e * (1.f / 255.f);
            }
        }
#pragma unroll
        for (int c = 0; c < 3; c++)
            *(float4*)(out + (size_t)(n * 3 + c) * H0 * W0
                           + (size_t)(4 * m + py) * W0 + 4 * q) = o[c];
    }
}

// ---------------------------------------------------------------------------
// Launch (4 kernels total)
// ---------------------------------------------------------------------------
static inline int nblk(long long n, int t) { return (int)((n + t - 1) / t); }

extern "C" void kernel_launch(void* const* d_in, const int* in_sizes, int n_in,
                              void* d_out, int out_size) {
    const float* x = (const float*)d_in[0];
    float* out = (float*)d_out;

    float *p1, *p2, *t80;
    cudaGetSymbolAddress((void**)&p1, g_pyr1);
    cudaGetSymbolAddress((void**)&p2, g_pyr2);
    cudaGetSymbolAddress((void**)&t80, g_t80);

    const int PREP_SMEM = 37325 * 4;
    cudaFuncSetAttribute(prep_kernel,
                         cudaFuncAttributeMaxDynamicSharedMemorySize, PREP_SMEM);

    const int T = 256;
    pyrdown16_kernel<<<nblk((long long)NPLANES * 160 * 160, T), T>>>(x,  p1, 1280, 1280);
    pyrdown16_kernel<<<nblk((long long)NPLANES * 80 * 80,  T), T>>>(p1, p2, 640, 640);
    prep_kernel<<<dim3(NPLANES, 3), 256, PREP_SMEM>>>(p2, t80);
    composite_kernel<<<dim3(20, 20, 8), 256>>>(x, t80, out);
}

// round 10
// speedup vs baseline: 1.2690x; 1.2690x over previous
#include <cuda_runtime.h>
#include <math.h>

#define NPLANES 24
#define H0 1280
#define W0 1280

// ---------------------------------------------------------------------------
// Scratch
// ---------------------------------------------------------------------------
__device__ float g_pyr1[NPLANES * 640 * 640];
__device__ float g_pyr2[NPLANES * 320 * 320];
__device__ float g_pyr3[NPLANES * 160 * 160];
__device__ float g_pyr4[NPLANES * 80 * 80];
__device__ float g_t80[3 * NPLANES * 80 * 80];   // filter results at 80 level

__device__ __forceinline__ int refl101(int i, int n) {
    if (i < 0) i = -i;
    if (i >= n) i = 2 * n - 2 - i;
    return i;
}

// ---------------------------------------------------------------------------
// f32x2 packed helpers (Blackwell)
// ---------------------------------------------------------------------------
typedef unsigned long long ull;
__device__ __forceinline__ ull pk2(float a, float b) {
    ull r;
    asm("mov.b64 %0, {%1, %2};" : "=l"(r)
        : "r"(__float_as_uint(a)), "r"(__float_as_uint(b)));
    return r;
}
__device__ __forceinline__ void upk2(ull v, float& a, float& b) {
    unsigned int lo, hi;
    asm("mov.b64 {%0, %1}, %2;" : "=r"(lo), "=r"(hi) : "l"(v));
    a = __uint_as_float(lo);
    b = __uint_as_float(hi);
}
__device__ __forceinline__ ull fma2(ull a, ull b, ull c) {
    ull r;
    asm("fma.rn.f32x2 %0, %1, %2, %3;" : "=l"(r) : "l"(a), "l"(b), "l"(c));
    return r;
}
__device__ __forceinline__ ull mul2(ull a, ull b) {
    ull r;
    asm("mul.rn.f32x2 %0, %1, %2;" : "=l"(r) : "l"(a), "l"(b));
    return r;
}

// ---------------------------------------------------------------------------
// pyrDown, 4x4 outputs/thread (proven in R8).
// ---------------------------------------------------------------------------
__global__ void __launch_bounds__(256)
pyrdown16_kernel(const float* __restrict__ src,
                 float* __restrict__ dst, int H, int W) {
    const int Ho = H >> 1, Wo = W >> 1;
    const int Wq = Wo >> 2, Hq = Ho >> 2;
    const int total = NPLANES * Hq * Wq;
    int idx = blockIdx.x * blockDim.x + threadIdx.x;
    if (idx >= total) return;
    int wq = idx % Wq;
    int t  = idx / Wq;
    int hq = t % Hq;
    int p  = t / Hq;
    int ho0 = hq << 2, wo0 = wq << 2;

    const float* s = src + (size_t)p * H * W;
    const float kk[5] = {0.0625f, 0.25f, 0.375f, 0.25f, 0.0625f};
    float* dbase = dst + (size_t)p * Ho * Wo;

    bool interior = (ho0 >= 1) && (2 * ho0 + 8 <= H - 1) &&
                    (wq >= 1) && (8 * wq + 11 <= W - 1);
    if (interior) {
        float hs[11][4];
        const float* rowp = s + (size_t)(2 * ho0 - 2) * W + (8 * wq - 4);
#pragma unroll
        for (int r = 0; r < 11; r++, rowp += W) {
            const float4* r4 = (const float4*)rowp;
            float4 A = r4[0], Bv = r4[1], C = r4[2], D = r4[3];
            float v[16] = {A.x, A.y, A.z, A.w, Bv.x, Bv.y, Bv.z, Bv.w,
                           C.x, C.y, C.z, C.w, D.x, D.y, D.z, D.w};
#pragma unroll
            for (int o = 0; o < 4; o++)
                hs[r][o] = 0.0625f * (v[2 * o + 2] + v[2 * o + 6])
                         + 0.25f   * (v[2 * o + 3] + v[2 * o + 5])
                         + 0.375f  *  v[2 * o + 4];
        }
#pragma unroll
        for (int ry = 0; ry < 4; ry++) {
            float4 o4;
            float* acc = (float*)&o4;
#pragma unroll
            for (int o = 0; o < 4; o++) {
                float a = 0.f;
#pragma unroll
                for (int dy = 0; dy < 5; dy++)
                    a += kk[dy] * hs[2 * ry + dy][o];
                acc[o] = a;
            }
            *(float4*)(dbase + (size_t)(ho0 + ry) * Wo + wo0) = o4;
        }
    } else {
#pragma unroll
        for (int ry = 0; ry < 4; ry++) {
            int ho = ho0 + ry;
            float4 o4;
            float* acc = (float*)&o4;
#pragma unroll
            for (int o = 0; o < 4; o++) {
                int wo = wo0 + o;
                float a = 0.f;
#pragma unroll
                for (int dy = 0; dy < 5; dy++) {
                    int y = refl101(2 * ho + dy - 2, H);
                    const float* row = s + (size_t)y * W;
                    float r2 = 0.f;
#pragma unroll
                    for (int dx = 0; dx < 5; dx++)
                        r2 += kk[dx] * row[refl101(2 * wo + dx - 2, W)];
                    a += kk[dy] * r2;
                }
                acc[o] = a;
            }
            *(float4*)(dbase + (size_t)ho * Wo + wo0) = o4;
        }
    }
}

// ---------------------------------------------------------------------------
// Generic-pointer per-plane helpers (smem or gmem)
// ---------------------------------------------------------------------------
__device__ void pyrdown_plane(const float* s, float* d, int N, int tid, int nt) {
    const int No = N >> 1;
    const int total = No * No;
    const float kk[5] = {0.0625f, 0.25f, 0.375f, 0.25f, 0.0625f};
    for (int idx = tid; idx < total; idx += nt) {
        int wo = idx % No, ho = idx / No;
        float acc = 0.f;
#pragma unroll
        for (int dy = 0; dy < 5; dy++) {
            int y = refl101(2 * ho + dy - 2, N);
            const float* row = s + y * N;
            float r = 0.f;
#pragma unroll
            for (int dx = 0; dx < 5; dx++)
                r += kk[dx] * row[refl101(2 * wo + dx - 2, N)];
            acc += kk[dy] * r;
        }
        d[idx] = acc;
    }
}

__device__ void up2_plane(const float* s, float* d, int N, int tid, int nt) {
    const int No = 2 * N;
    const int total = No * No;
    for (int idx = tid; idx < total; idx += nt) {
        int wo = idx % No, ho = idx / No;
        int iy = (ho >> 1) + (ho & 1) - 1;
        float fy = (ho & 1) ? 0.25f : 0.75f;
        int y0 = max(iy, 0), y1 = min(iy + 1, N - 1);
        int ix = (wo >> 1) + (wo & 1) - 1;
        float fx = (wo & 1) ? 0.25f : 0.75f;
        int x0 = max(ix, 0), x1 = min(ix + 1, N - 1);
        float v00 = s[y0 * N + x0], v01 = s[y0 * N + x1];
        float v10 = s[y1 * N + x0], v11 = s[y1 * N + x1];
        float tp = v00 + fx * (v01 - v00);
        float bt = v10 + fx * (v11 - v10);
        d[idx] = tp + fy * (bt - tp);
    }
}

__device__ void blur_plane(const float* s, float* d, int N, int ks,
                           int tid, int nt) {
    float g[9];
    float sg = 0.3f * ((ks - 1) * 0.5f - 1.f) + 0.8f;
    float inv2s2 = 1.f / (2.f * sg * sg);
    float sum = 0.f;
    for (int i = 0; i < ks; i++) {
        float dd = (float)i - (ks - 1) * 0.5f;
        g[i] = expf(-dd * dd * inv2s2);
        sum += g[i];
    }
    float inv = 1.f / sum;
    for (int i = 0; i < ks; i++) g[i] *= inv;

    int P = ks / 2;
    const int total = N * N;
    for (int idx = tid; idx < total; idx += nt) {
        int w = idx % N, h = idx / N;
        float acc = 0.f;
        for (int dy = 0; dy < ks; dy++) {
            int y = refl101(h + dy - P, N);
            const float* row = s + y * N;
            float r = 0.f;
            for (int dx = 0; dx < ks; dx++)
                r += g[dx] * row[refl101(w + dx - P, N)];
            acc += g[dy] * r;
        }
        d[idx] = acc;
    }
}

// ---------------------------------------------------------------------------
// prep (R8 version): block = (plane, sigma). Loads the 80-level plane into
// static smem, builds small pyramid + blur + up-chain in smem, writes the
// 80-level filter result.
// ---------------------------------------------------------------------------
__global__ void __launch_bounds__(256)
prep_kernel(const float* __restrict__ p4, float* __restrict__ t80) {
    __shared__ float s80[6400];
    __shared__ float s40[1600];
    __shared__ float s20[400];
    __shared__ float s10[100];
    __shared__ float s5[25];
    __shared__ float A[1600];
    __shared__ float B[1600];

    int p = blockIdx.x;
    int sg = blockIdx.y;
    int tid = threadIdx.x, nt = blockDim.x;

    const float4* src4 = (const float4*)(p4 + (size_t)p * 6400);
    for (int i = tid; i < 1600; i += nt)
        ((float4*)s80)[i] = src4[i];
    __syncthreads();

    pyrdown_plane(s80, s40, 80, tid, nt);
    __syncthreads();
    if (sg >= 1) {
        pyrdown_plane(s40, s20, 40, tid, nt);
        __syncthreads();
        pyrdown_plane(s20, s10, 20, tid, nt);
        __syncthreads();
    }
    if (sg == 2) {
        pyrdown_plane(s10, s5, 10, tid, nt);
        __syncthreads();
    }

    float* T = t80 + ((size_t)sg * NPLANES + p) * 6400;

    if (sg == 0) {
        blur_plane(s40, A, 40, 7, tid, nt); __syncthreads();
        up2_plane(A, T, 40, tid, nt);
    } else if (sg == 1) {
        blur_plane(s10, A, 10, 9, tid, nt); __syncthreads();
        up2_plane(A, B, 10, tid, nt); __syncthreads();
        up2_plane(B, A, 20, tid, nt); __syncthreads();
        up2_plane(A, T, 40, tid, nt);
    } else {
        blur_plane(s5, A, 5, 9, tid, nt); __syncthreads();
        up2_plane(A, B, 5, tid, nt); __syncthreads();
        up2_plane(B, A, 10, tid, nt); __syncthreads();
        up2_plane(A, B, 20, tid, nt); __syncthreads();
        up2_plane(B, T, 40, tid, nt);
    }
}

// ---------------------------------------------------------------------------
// Composed 16-phase, 3-tap polyphase weights for the quadruple upsample
// (80 -> 320 -> 1280, two chained double-ups). Output row 16*M + p draws
// 80-rows {M-1, M, M+1} (clamped). Exact dyadic composition of W4 ∘ W4.
// ---------------------------------------------------------------------------
__device__ __constant__ float W16[16][3] = {
    {0.46875f,    0.53125f,   0.f},
    {0.41015625f, 0.5859375f, 0.00390625f},
    {0.35546875f, 0.6328125f, 0.01171875f},
    {0.3046875f,  0.671875f,  0.0234375f},
    {0.2578125f,  0.703125f,  0.0390625f},
    {0.21484375f, 0.7265625f, 0.05859375f},
    {0.17578125f, 0.7421875f, 0.08203125f},
    {0.140625f,   0.75f,      0.109375f},
    {0.109375f,   0.75f,      0.140625f},
    {0.08203125f, 0.7421875f, 0.17578125f},
    {0.05859375f, 0.7265625f, 0.21484375f},
    {0.0390625f,  0.703125f,  0.2578125f},
    {0.0234375f,  0.671875f,  0.3046875f},
    {0.01171875f, 0.6328125f, 0.35546875f},
    {0.00390625f, 0.5859375f, 0.41015625f},
    {0.f,         0.53125f,   0.46875f}
};

// ---------------------------------------------------------------------------
// Composite: block = 128 threads = 8x16 320-cells; thread = one 320-cell
// = 4x4 output pixels x 3 channels. Filters sampled DIRECTLY from the
// 80-level t80 via the composed W16 3-tap stencil (smem 4x6 patch per
// sigma/channel). No intermediate pack buffer.
// ---------------------------------------------------------------------------
__global__ void __launch_bounds__(128)
composite_kernel(const float* __restrict__ x,
                 const float* __restrict__ t80,
                 float* __restrict__ out) {
    __shared__ float2 SAB[3][4][6];   // (f30, f150)
    __shared__ float  SZ [3][4][6];   // f300

    int n   = blockIdx.z;
    int bm0 = blockIdx.y * 8;    // 320-cell row base
    int bq0 = blockIdx.x * 16;   // 320-cell col base
    int tid = threadIdx.x;

    // ---- Stage A: 4x6 80-level patch per (channel) for all 3 sigmas ----
    int R0 = (bm0 >> 2) - 1, Q0 = (bq0 >> 2) - 1;
    if (tid < 72) {
        int c = tid / 24;
        int cell = tid - c * 24;
        int i = cell / 6, j = cell - i * 6;
        int gr = min(max(R0 + i, 0), 79);
        int gc = min(max(Q0 + j, 0), 79);
        int off = (n * 3 + c) * 6400 + gr * 80 + gc;
        float f0 = t80[off];
        float f1 = t80[NPLANES * 6400 + off];
        float f2 = t80[2 * NPLANES * 6400 + off];
        SAB[c][i][j] = make_float2(f0, f1);
        SZ[c][i][j] = f2;
    }
    __syncthreads();

    int ty = tid >> 4, tx = tid & 15;
    int m = bm0 + ty, q = bq0 + tx;
    int lr = ty >> 2, lc = tx >> 2;          // local patch base (row, col)
    int prb = (ty & 3) * 4, pcb = (tx & 3) * 4;  // phase bases

    const float EPS = 1e-6f;
    const float LOG10_2 = 0.30102999566398f;
    const float* xb = x + (size_t)n * 3 * H0 * W0;
    float* ob = out + (size_t)n * 3 * H0 * W0;

    // ---- inv_sum pass (all channels of x) ----
    float inv_sum[16];
#pragma unroll
    for (int py = 0; py < 4; py++) {
        size_t ro = (size_t)(4 * m + py) * W0 + 4 * q;
        float4 x0 = *(const float4*)(xb + ro);
        float4 x1 = *(const float4*)(xb + (size_t)H0 * W0 + ro);
        float4 x2 = *(const float4*)(xb + (size_t)2 * H0 * W0 + ro);
#pragma unroll
        for (int px = 0; px < 4; px++) {
            float s = (((const float*)&x0)[px] + ((const float*)&x1)[px]
                     + ((const float*)&x2)[px]) * 255.f + 3.f;
            inv_sum[py * 4 + px] = 2.f / (s + EPS);
        }
    }

    // ---- per channel: filter sample + retinex + output ----
#pragma unroll
    for (int c = 0; c < 3; c++) {
        ull  Pab[3][3];
        float Pz[3][3];
#pragma unroll
        for (int a = 0; a < 3; a++)
#pragma unroll
            for (int b = 0; b < 3; b++) {
                float2 v = SAB[c][lr + a][lc + b];
                Pab[a][b] = pk2(v.x, v.y);
                Pz[a][b]  = SZ[c][lr + a][lc + b];
            }

        const float* xc = xb + (size_t)c * H0 * W0;
        float* oc = ob + (size_t)c * H0 * W0;

#pragma unroll
        for (int py = 0; py < 4; py++) {
            float wy0 = W16[prb + py][0], wy1 = W16[prb + py][1],
                  wy2 = W16[prb + py][2];
            ull wy0p = pk2(wy0, wy0), wy1p = pk2(wy1, wy1), wy2p = pk2(wy2, wy2);
            ull Rab[3];
            float Rz[3];
#pragma unroll
            for (int b = 0; b < 3; b++) {
                Rab[b] = fma2(Pab[2][b], wy2p,
                         fma2(Pab[1][b], wy1p,
                         mul2(Pab[0][b], wy0p)));
                Rz[b] = wy0 * Pz[0][b] + wy1 * Pz[1][b] + wy2 * Pz[2][b];
            }

            size_t ro = (size_t)(4 * m + py) * W0 + 4 * q;
            float4 xr = *(const float4*)(xc + ro);
            float4 o;
#pragma unroll
            for (int px = 0; px < 4; px++) {
                float wx0 = W16[pcb + px][0], wx1 = W16[pcb + px][1],
                      wx2 = W16[pcb + px][2];
                ull vab = fma2(Rab[2], pk2(wx2, wx2),
                          fma2(Rab[1], pk2(wx1, wx1),
                          mul2(Rab[0], pk2(wx0, wx0))));
                float vz = wx0 * Rz[0] + wx1 * Rz[1] + wx2 * Rz[2];
                float va, vb;
                upk2(vab, va, vb);
                float fa = 255.f * va + 1.f;
                float fb = 255.f * vb + 1.f;
                float fc = 255.f * vz + 1.f;
                float lpv = __log2f((fa + EPS) * (fb + EPS) * (fc + EPS));

                float im = ((const float*)&xr)[px] * 255.f + 1.f;
                float retinex = (__log2f(im + EPS) - lpv * (1.f / 3.f)) * LOG10_2;
                float cr = __log2f(im * inv_sum[py * 4 + px] + 1.f) * LOG10_2;
                float e = retinex * cr * 2700.f + 128.f;
                e = fminf(fmaxf(e, 0.f), 255.f);
                ((float*)&o)[px] = e * (1.f / 255.f);
            }
            *(float4*)(oc + ro) = o;
        }
    }
}

// ---------------------------------------------------------------------------
// Launch (6 kernels)
// ---------------------------------------------------------------------------
static inline int nblk(long long n, int t) { return (int)((n + t - 1) / t); }

extern "C" void kernel_launch(void* const* d_in, const int* in_sizes, int n_in,
                              void* d_out, int out_size) {
    const float* x = (const float*)d_in[0];
    float* out = (float*)d_out;

    float *p1, *p2, *p3, *p4, *t80;
    cudaGetSymbolAddress((void**)&p1, g_pyr1);
    cudaGetSymbolAddress((void**)&p2, g_pyr2);
    cudaGetSymbolAddress((void**)&p3, g_pyr3);
    cudaGetSymbolAddress((void**)&p4, g_pyr4);
    cudaGetSymbolAddress((void**)&t80, g_t80);

    const int T = 256;
    pyrdown16_kernel<<<nblk((long long)NPLANES * 160 * 160, T), T>>>(x,  p1, 1280, 1280);
    pyrdown16_kernel<<<nblk((long long)NPLANES * 80 * 80,   T), T>>>(p1, p2, 640, 640);
    pyrdown16_kernel<<<nblk((long long)NPLANES * 40 * 40,   T), T>>>(p2, p3, 320, 320);
    pyrdown16_kernel<<<nblk((long long)NPLANES * 20 * 20,   T), T>>>(p3, p4, 160, 160);
    prep_kernel<<<dim3(NPLANES, 3), 256>>>(p4, t80);
    composite_kernel<<<dim3(20, 40, 8), 128>>>(x, t80, out);
}